// round 2
// baseline (speedup 1.0000x reference)
#include <cuda_runtime.h>

// ---------------- problem constants ----------------
#define DIN 32
#define KSEQ 512
#define PD 64
#define DM 128
#define NL 4
#define PL 8
#define STR 4
#define DI 256          // 2*DM
#define DS 16
#define DC 4
#define DTR 8
#define NSEQ 127        // (KSEQ-PL)/STR + 1
#define BATCH 32
#define MSEQ (BATCH*PD)         // 2048 sequences
#define NTOK (MSEQ*NSEQ)        // 260096 tokens
#define XPJ (DTR + 2*DS)        // 40

// ---------------- scratch (device globals; no allocation allowed) ----------------
// g_xr doubles as the scan output buffer: xr is consumed by the in-proj GEMM,
// after which the same space holds y (gated scan output) for the out-proj GEMM.
__device__ float g_h  [BATCH*KSEQ*PD];     // front output          (4 MB)
__device__ float g_e  [NTOK*DM];           // residual stream     (133 MB)
__device__ float g_xr [NTOK*DI];           // rms-normed in / y   (266 MB)
__device__ float g_uz [NTOK*2*DI];         // in-proj output      (532 MB)
__device__ float g_u  [NTOK*DI];           // conv+silu output    (266 MB)
__device__ float g_dbc[NTOK*XPJ];          // xproj output         (42 MB)
__device__ float g_y1 [MSEQ];

// ---------------- FMA-only transcendentals (avoid MUFU serialization) ----------
__device__ __forceinline__ float fexp(float x) {
    x = fminf(fmaxf(x, -87.0f), 87.0f);
    float t  = x * 1.4426950408889634f;
    float fi = floorf(t);
    float f  = t - fi;
    float p  = 1.5252733804059841e-05f;
    p = fmaf(p, f, 1.5403530393381608e-04f);
    p = fmaf(p, f, 1.3333558146428443e-03f);
    p = fmaf(p, f, 9.6181291076284770e-03f);
    p = fmaf(p, f, 5.5504108664821580e-02f);
    p = fmaf(p, f, 2.4022650695910070e-01f);
    p = fmaf(p, f, 6.9314718055994530e-01f);
    p = fmaf(p, f, 1.0f);
    int ei = (int)fi;
    float sc = __int_as_float((ei + 127) << 23);
    return p * sc;
}

__device__ __forceinline__ float flog(float x) {
    int ix = __float_as_int(x);
    int e  = ((ix >> 23) & 0xFF) - 127;
    float m = __int_as_float((ix & 0x007FFFFF) | 0x3F800000);
    if (m > 1.41421356f) { m *= 0.5f; e += 1; }
    float f = m - 1.0f;
    float z = f * f;
    float p = 7.0376836292e-2f;
    p = fmaf(p, f, -1.1514610310e-1f);
    p = fmaf(p, f,  1.1676998740e-1f);
    p = fmaf(p, f, -1.2420140846e-1f);
    p = fmaf(p, f,  1.4249322787e-1f);
    p = fmaf(p, f, -1.6668057665e-1f);
    p = fmaf(p, f,  2.0000714765e-1f);
    p = fmaf(p, f, -2.4999993993e-1f);
    p = fmaf(p, f,  3.3333331174e-1f);
    float r = f * z * p - 0.5f * z + f;
    return fmaf((float)e, 0.693147180559945f, r);
}

__device__ __forceinline__ float frcp_pos(float a) {
    float x = __int_as_float(0x7EF311C3 - __float_as_int(a));
    x = x * (2.0f - a * x);
    x = x * (2.0f - a * x);
    x = x * (2.0f - a * x);
    return x;
}

__device__ __forceinline__ float fsigmoid(float x) { return frcp_pos(1.0f + fexp(-x)); }
__device__ __forceinline__ float fsilu(float x)    { return x * fsigmoid(x); }

// ---------------- reduction helper (128-thread blocks) ----------------
__device__ __forceinline__ float block_reduce_128(float v, float* red) {
    #pragma unroll
    for (int o = 16; o > 0; o >>= 1) v += __shfl_xor_sync(0xffffffffu, v, o);
    int w = threadIdx.x >> 5;
    __syncthreads();
    if ((threadIdx.x & 31) == 0) red[w] = v;
    __syncthreads();
    return red[0] + red[1] + red[2] + red[3];
}

// ---------------- 1) front: h = LN(x @ proj_w + proj_b) ----------------
__global__ void front_kernel(const float* __restrict__ x,  const float* __restrict__ pw,
                             const float* __restrict__ pb, const float* __restrict__ lw,
                             const float* __restrict__ lb) {
    int row = blockIdx.x;          // b*KSEQ + k
    int pd  = threadIdx.x;         // 64
    __shared__ float xr[DIN];
    __shared__ float red[2];
    if (pd < DIN) xr[pd] = x[row * DIN + pd];
    __syncthreads();
    float acc = pb[pd];
    #pragma unroll
    for (int i = 0; i < DIN; i++) acc = fmaf(xr[i], pw[i * PD + pd], acc);
    float s = acc;
    #pragma unroll
    for (int o = 16; o > 0; o >>= 1) s += __shfl_xor_sync(0xffffffffu, s, o);
    if ((pd & 31) == 0) red[pd >> 5] = s;
    __syncthreads();
    float mu = (red[0] + red[1]) * (1.0f / PD);
    __syncthreads();
    float d = acc - mu;
    float q = d * d;
    #pragma unroll
    for (int o = 16; o > 0; o >>= 1) q += __shfl_xor_sync(0xffffffffu, q, o);
    if ((pd & 31) == 0) red[pd >> 5] = q;
    __syncthreads();
    float var = (red[0] + red[1]) * (1.0f / PD);
    g_h[row * PD + pd] = d * rsqrtf(var + 1e-5f) * lw[pd] + lb[pd];
}

// ---------------- 2) patch embed ----------------
__global__ void patch_kernel(const float* __restrict__ patch_w, const float* __restrict__ patch_b) {
    int n  = blockIdx.x;           // NSEQ
    int m  = blockIdx.y;           // MSEQ
    int dm = threadIdx.x;          // 128
    int b  = m >> 6, pd = m & 63;
    __shared__ float hv[PL];
    if (dm < PL) hv[dm] = g_h[(b * KSEQ + n * STR + dm) * PD + pd];
    __syncthreads();
    float acc = patch_b[dm];
    #pragma unroll
    for (int pl = 0; pl < PL; pl++) acc = fmaf(hv[pl], patch_w[pl * DM + dm], acc);
    g_e[((size_t)m * NSEQ + n) * DM + dm] = acc;
}

// ---------------- 3) per-token RMS norm: xr = rms(e)*norm_w ----------------
__global__ void rms_kernel(const float* __restrict__ nw) {
    size_t tok = blockIdx.x;
    int j = threadIdx.x;           // 128
    __shared__ float red[4];
    float v = g_e[tok * DM + j];
    float ss = block_reduce_128(v * v, red);
    g_xr[tok * DM + j] = v * rsqrtf(ss * (1.0f / DM) + 1e-5f) * nw[j];
}

// ---------------- generic tiled fp32 GEMM: C[M,N] (=|+=) A[M,K] @ B[K,N] ----------
// Requires M % 64 == 0, K % 16 == 0, N % 4 == 0, lda/ldb multiples of 4.
template<bool ACC>
__global__ void __launch_bounds__(256)
gemm_kernel(const float* __restrict__ A, int lda,
            const float* __restrict__ B, int ldb,
            float* __restrict__ C, int ldc, int N, int K) {
    __shared__ float As[16][64];
    __shared__ float Bs[16][64];
    const int tid = threadIdx.x;           // 256
    const int tx = tid & 15, ty = tid >> 4;
    const int row0 = blockIdx.y * 64;
    const int col0 = blockIdx.x * 64;
    const int arow = tid >> 2;
    const int acol = (tid & 3) << 2;
    const int brow = tid >> 4;
    const int bcol = (tid & 15) << 2;
    float acc[4][4];
    #pragma unroll
    for (int i = 0; i < 4; i++)
        #pragma unroll
        for (int j = 0; j < 4; j++) acc[i][j] = 0.f;

    for (int k0 = 0; k0 < K; k0 += 16) {
        float4 av = *(const float4*)(A + (size_t)(row0 + arow) * lda + k0 + acol);
        As[acol + 0][arow] = av.x; As[acol + 1][arow] = av.y;
        As[acol + 2][arow] = av.z; As[acol + 3][arow] = av.w;
        float4 bv = make_float4(0.f, 0.f, 0.f, 0.f);
        if (col0 + bcol < N)
            bv = *(const float4*)(B + (size_t)(k0 + brow) * ldb + col0 + bcol);
        Bs[brow][bcol + 0] = bv.x; Bs[brow][bcol + 1] = bv.y;
        Bs[brow][bcol + 2] = bv.z; Bs[brow][bcol + 3] = bv.w;
        __syncthreads();
        #pragma unroll
        for (int kk = 0; kk < 16; kk++) {
            float4 aq = *(const float4*)&As[kk][ty << 2];
            float4 bq = *(const float4*)&Bs[kk][tx << 2];
            acc[0][0] = fmaf(aq.x, bq.x, acc[0][0]);
            acc[0][1] = fmaf(aq.x, bq.y, acc[0][1]);
            acc[0][2] = fmaf(aq.x, bq.z, acc[0][2]);
            acc[0][3] = fmaf(aq.x, bq.w, acc[0][3]);
            acc[1][0] = fmaf(aq.y, bq.x, acc[1][0]);
            acc[1][1] = fmaf(aq.y, bq.y, acc[1][1]);
            acc[1][2] = fmaf(aq.y, bq.z, acc[1][2]);
            acc[1][3] = fmaf(aq.y, bq.w, acc[1][3]);
            acc[2][0] = fmaf(aq.z, bq.x, acc[2][0]);
            acc[2][1] = fmaf(aq.z, bq.y, acc[2][1]);
            acc[2][2] = fmaf(aq.z, bq.z, acc[2][2]);
            acc[2][3] = fmaf(aq.z, bq.w, acc[2][3]);
            acc[3][0] = fmaf(aq.w, bq.x, acc[3][0]);
            acc[3][1] = fmaf(aq.w, bq.y, acc[3][1]);
            acc[3][2] = fmaf(aq.w, bq.z, acc[3][2]);
            acc[3][3] = fmaf(aq.w, bq.w, acc[3][3]);
        }
        __syncthreads();
    }
    #pragma unroll
    for (int i = 0; i < 4; i++) {
        int r = row0 + (ty << 2) + i;
        #pragma unroll
        for (int j = 0; j < 4; j++) {
            int c = col0 + (tx << 2) + j;
            if (c < N) {
                size_t off = (size_t)r * ldc + c;
                if (ACC) C[off] += acc[i][j]; else C[off] = acc[i][j];
            }
        }
    }
}

// ---------------- 4) depthwise causal conv (DC=4) + SiLU ----------------
__global__ void conv_kernel(const float* __restrict__ cw, const float* __restrict__ cb) {
    int m = blockIdx.x;            // MSEQ
    int d = threadIdx.x;           // DI
    float w0 = cw[d * DC + 0], w1 = cw[d * DC + 1], w2 = cw[d * DC + 2], w3 = cw[d * DC + 3];
    float bias = cb[d];
    float x0 = 0.f, x1 = 0.f, x2 = 0.f;
    const float* up = g_uz + (size_t)m * NSEQ * 2 * DI + d;
    float*       op = g_u  + (size_t)m * NSEQ * DI + d;
    for (int t = 0; t < NSEQ; t++) {
        float xt = up[(size_t)t * 2 * DI];
        float uc = bias;
        uc = fmaf(x0, w0, uc);
        uc = fmaf(x1, w1, uc);
        uc = fmaf(x2, w2, uc);
        uc = fmaf(xt, w3, uc);
        op[(size_t)t * DI] = fsilu(uc);
        x0 = x1; x1 = x2; x2 = xt;
    }
}

// ---------------- 5) fused dt-proj + softplus + selective scan + output gate -------
// Writes the gated output into g_xr (reusing the dead xr buffer).
__global__ void scan_kernel(const float* __restrict__ dtw, const float* __restrict__ dtbp,
                            const float* __restrict__ alog, const float* __restrict__ dpp) {
    int m = blockIdx.x;            // MSEQ
    int d = threadIdx.x;           // DI
    __shared__ float s_dtw[DTR * DI];        // 8KB
    __shared__ float s40[2][XPJ];            // double-buffered dt/B/C per timestep
    for (int i = d; i < DTR * DI; i += DI) s_dtw[i] = dtw[i];
    float dtb = dtbp[d];
    float Dpv = dpp[d];
    bool fast = true;
    #pragma unroll
    for (int s = 0; s < DS; s++) {
        float as = -fexp(alog[d * DS + s]);
        fast = fast && (fabsf(as + (float)(s + 1)) < 1e-3f);
    }
    float hst[DS];
    #pragma unroll
    for (int s = 0; s < DS; s++) hst[s] = 0.f;

    const float* dbc = g_dbc + (size_t)m * NSEQ * XPJ;
    if (d < XPJ) s40[0][d] = dbc[d];
    __syncthreads();

    for (int t = 0; t < NSEQ; t++) {
        int cur = t & 1;
        if (t + 1 < NSEQ && d < XPJ) s40[cur ^ 1][d] = dbc[(size_t)(t + 1) * XPJ + d];
        float u_td = g_u[((size_t)m * NSEQ + t) * DI + d];
        float v = dtb;
        #pragma unroll
        for (int i = 0; i < DTR; i++) v = fmaf(s40[cur][i], s_dtw[i * DI + d], v);
        float delta = (v > 15.f) ? v : flog(1.0f + fexp(v));   // softplus
        float du = delta * u_td;
        float y = 0.f;
        if (fast) {
            // A_s == -(s+1): dA_s = exp(-delta)^(s+1)
            float r = fexp(-delta);
            float p = r;
            #pragma unroll
            for (int s = 0; s < DS; s++) {
                hst[s] = fmaf(p, hst[s], du * s40[cur][DTR + s]);
                y = fmaf(hst[s], s40[cur][DTR + DS + s], y);
                p *= r;
            }
        } else {
            #pragma unroll
            for (int s = 0; s < DS; s++) {
                float as = -fexp(alog[d * DS + s]);
                float dA = fexp(delta * as);
                hst[s] = fmaf(dA, hst[s], du * s40[cur][DTR + s]);
                y = fmaf(hst[s], s40[cur][DTR + DS + s], y);
            }
        }
        float yo = fmaf(u_td, Dpv, y);
        float z = g_uz[((size_t)m * NSEQ + t) * 2 * DI + DI + d];
        g_xr[((size_t)m * NSEQ + t) * DI + d] = yo * fsilu(z);   // gate fused here
        __syncthreads();
    }
}

// ---------------- 6) final RMS + bb dot per sequence ----------------
__global__ void bb_kernel(const float* __restrict__ fnw, const float* __restrict__ bbw,
                          const float* __restrict__ bbb) {
    int m = blockIdx.x;            // MSEQ
    int j = threadIdx.x;           // 128
    __shared__ float red[4];
    float fw = fnw[j];
    float acc = 0.f;
    for (int n = 0; n < NSEQ; n++) {
        float v = g_e[((size_t)m * NSEQ + n) * DM + j];
        float ss = block_reduce_128(v * v, red);
        float scale = rsqrtf(ss * (1.0f / DM) + 1e-5f);
        acc = fmaf(v * scale * fw, bbw[n * DM + j], acc);
    }
    float tot = block_reduce_128(acc, red);
    if (j == 0) g_y1[m] = tot + bbb[0];
}

// ---------------- 7) head ----------------
__global__ void head_kernel(const float* __restrict__ hw, const float* __restrict__ hb,
                            float* __restrict__ out) {
    int t = threadIdx.x;           // 64
    int b = t >> 1, j = t & 1;
    float acc = hb[j];
    #pragma unroll
    for (int p = 0; p < PD; p++) acc = fmaf(g_y1[b * PD + p], hw[p * 2 + j], acc);
    out[b * 2 + j] = acc;
}

// ---------------- launch ----------------
extern "C" void kernel_launch(void* const* d_in, const int* in_sizes, int n_in,
                              void* d_out, int out_size) {
    const float* x       = (const float*)d_in[0];
    const float* proj_w  = (const float*)d_in[1];
    const float* proj_b  = (const float*)d_in[2];
    const float* ln_w    = (const float*)d_in[3];
    const float* ln_b    = (const float*)d_in[4];
    const float* patch_w = (const float*)d_in[5];
    const float* patch_b = (const float*)d_in[6];
    const float* in_w    = (const float*)d_in[7];
    const float* conv_w  = (const float*)d_in[8];
    const float* conv_b  = (const float*)d_in[9];
    const float* xproj_w = (const float*)d_in[10];
    const float* dt_w    = (const float*)d_in[11];
    const float* dt_b    = (const float*)d_in[12];
    const float* A_log   = (const float*)d_in[13];
    const float* Dp      = (const float*)d_in[14];
    const float* out_w   = (const float*)d_in[15];
    const float* norm_w  = (const float*)d_in[16];
    const float* fnorm_w = (const float*)d_in[17];
    const float* bb_w    = (const float*)d_in[18];
    const float* bb_b    = (const float*)d_in[19];
    const float* head_w  = (const float*)d_in[20];
    const float* head_b  = (const float*)d_in[21];
    float* out = (float*)d_out;

    float *xr, *uz, *u, *dbc, *e;
    cudaGetSymbolAddress((void**)&xr,  g_xr);
    cudaGetSymbolAddress((void**)&uz,  g_uz);
    cudaGetSymbolAddress((void**)&u,   g_u);
    cudaGetSymbolAddress((void**)&dbc, g_dbc);
    cudaGetSymbolAddress((void**)&e,   g_e);

    front_kernel<<<BATCH * KSEQ, PD>>>(x, proj_w, proj_b, ln_w, ln_b);
    patch_kernel<<<dim3(NSEQ, MSEQ), DM>>>(patch_w, patch_b);

    for (int l = 0; l < NL; l++) {
        rms_kernel<<<NTOK, DM>>>(norm_w + l * DM);
        // uz = xr @ in_w[l]   (260096 x 128 x 512)
        gemm_kernel<false><<<dim3(2 * DI / 64, NTOK / 64), 256>>>(
            xr, DM, in_w + (size_t)l * DM * 2 * DI, 2 * DI, uz, 2 * DI, 2 * DI, DM);
        conv_kernel<<<MSEQ, DI>>>(conv_w + (size_t)l * DI * DC, conv_b + (size_t)l * DI);
        // dbc = u @ xproj_w[l]  (260096 x 256 x 40)
        gemm_kernel<false><<<dim3(1, NTOK / 64), 256>>>(
            u, DI, xproj_w + (size_t)l * DI * XPJ, XPJ, dbc, XPJ, XPJ, DI);
        scan_kernel<<<MSEQ, DI>>>(dt_w + (size_t)l * DTR * DI, dt_b + (size_t)l * DI,
                                  A_log + (size_t)l * DI * DS, Dp + (size_t)l * DI);
        // e += y_gated @ out_w[l]  (260096 x 256 x 128); y lives in g_xr now
        gemm_kernel<true><<<dim3(DM / 64, NTOK / 64), 256>>>(
            xr, DI, out_w + (size_t)l * DI * DM, DM, e, DM, DM, DI);
    }

    bb_kernel<<<MSEQ, DM>>>(fnorm_w, bb_w, bb_b);
    head_kernel<<<1, 64>>>(head_w, head_b, out);
}

// round 4
// speedup vs baseline: 1.4336x; 1.4336x over previous
#include <cuda_runtime.h>
#include <cuda_bf16.h>
#include <cstdint>

// ---------------- problem constants ----------------
#define DIN 32
#define KSEQ 512
#define PD 64
#define DM 128
#define NL 4
#define PL 8
#define STR 4
#define DI 256          // 2*DM
#define DS 16
#define DC 4
#define DTR 8
#define NSEQ 127        // (KSEQ-PL)/STR + 1
#define BATCH 32
#define MSEQ (BATCH*PD)         // 2048 sequences
#define NTOK (MSEQ*NSEQ)        // 260096 tokens
#define XPJ (DTR + 2*DS)        // 40

// ---------------- scratch (device globals; no allocation allowed) ----------------
__device__ float g_h  [BATCH*KSEQ*PD];
__device__ float g_e  [NTOK*DM];
__device__ float g_xr [NTOK*DI];           // rms-normed in / gated scan out (aliased)
__device__ float g_uz [NTOK*2*DI];
__device__ float g_u  [NTOK*DI];
__device__ float g_dbc[NTOK*XPJ];
__device__ float g_y1 [MSEQ];

// ---------------- FMA-only transcendentals ----------
__device__ __forceinline__ float fexp(float x) {
    x = fminf(fmaxf(x, -87.0f), 87.0f);
    float t  = x * 1.4426950408889634f;
    float fi = floorf(t);
    float f  = t - fi;
    float p  = 1.5252733804059841e-05f;
    p = fmaf(p, f, 1.5403530393381608e-04f);
    p = fmaf(p, f, 1.3333558146428443e-03f);
    p = fmaf(p, f, 9.6181291076284770e-03f);
    p = fmaf(p, f, 5.5504108664821580e-02f);
    p = fmaf(p, f, 2.4022650695910070e-01f);
    p = fmaf(p, f, 6.9314718055994530e-01f);
    p = fmaf(p, f, 1.0f);
    int ei = (int)fi;
    float sc = __int_as_float((ei + 127) << 23);
    return p * sc;
}

__device__ __forceinline__ float flog(float x) {
    int ix = __float_as_int(x);
    int e  = ((ix >> 23) & 0xFF) - 127;
    float m = __int_as_float((ix & 0x007FFFFF) | 0x3F800000);
    if (m > 1.41421356f) { m *= 0.5f; e += 1; }
    float f = m - 1.0f;
    float z = f * f;
    float p = 7.0376836292e-2f;
    p = fmaf(p, f, -1.1514610310e-1f);
    p = fmaf(p, f,  1.1676998740e-1f);
    p = fmaf(p, f, -1.2420140846e-1f);
    p = fmaf(p, f,  1.4249322787e-1f);
    p = fmaf(p, f, -1.6668057665e-1f);
    p = fmaf(p, f,  2.0000714765e-1f);
    p = fmaf(p, f, -2.4999993993e-1f);
    p = fmaf(p, f,  3.3333331174e-1f);
    float r = f * z * p - 0.5f * z + f;
    return fmaf((float)e, 0.693147180559945f, r);
}

__device__ __forceinline__ float frcp_pos(float a) {
    float x = __int_as_float(0x7EF311C3 - __float_as_int(a));
    x = x * (2.0f - a * x);
    x = x * (2.0f - a * x);
    x = x * (2.0f - a * x);
    return x;
}

__device__ __forceinline__ float fsigmoid(float x) { return frcp_pos(1.0f + fexp(-x)); }
__device__ __forceinline__ float fsilu(float x)    { return x * fsigmoid(x); }

__device__ __forceinline__ float block_reduce_128(float v, float* red) {
    #pragma unroll
    for (int o = 16; o > 0; o >>= 1) v += __shfl_xor_sync(0xffffffffu, v, o);
    int w = threadIdx.x >> 5;
    __syncthreads();
    if ((threadIdx.x & 31) == 0) red[w] = v;
    __syncthreads();
    return red[0] + red[1] + red[2] + red[3];
}

// ---------------- warp-MMA helpers (sm_80+ path; works at compute_100) ----------
__device__ __forceinline__ uint32_t smem_u32(const void* p) {
    uint32_t a;
    asm("{ .reg .u64 t; cvta.to.shared.u64 t, %1; cvt.u32.u64 %0, t; }" : "=r"(a) : "l"(p));
    return a;
}

__device__ __forceinline__ void ldm4(uint32_t* r, uint32_t addr) {
    asm volatile("ldmatrix.sync.aligned.m8n8.x4.shared.b16 {%0,%1,%2,%3}, [%4];"
                 : "=r"(r[0]), "=r"(r[1]), "=r"(r[2]), "=r"(r[3]) : "r"(addr));
}

__device__ __forceinline__ void mma16816(float* c, const uint32_t* a, const uint32_t* b) {
    asm volatile(
        "mma.sync.aligned.m16n8k16.row.col.f32.bf16.bf16.f32 "
        "{%0,%1,%2,%3}, {%4,%5,%6,%7}, {%8,%9}, {%0,%1,%2,%3};"
        : "+f"(c[0]), "+f"(c[1]), "+f"(c[2]), "+f"(c[3])
        : "r"(a[0]), "r"(a[1]), "r"(a[2]), "r"(a[3]), "r"(b[0]), "r"(b[1]));
}

__device__ __forceinline__ uint32_t pack_hi2(float x, float y) {
    __nv_bfloat16 hx = __float2bfloat16(x), hy = __float2bfloat16(y);
    return (uint32_t)__bfloat16_as_ushort(hx) | ((uint32_t)__bfloat16_as_ushort(hy) << 16);
}
__device__ __forceinline__ uint32_t pack_lo2(float x, float y, uint32_t hi) {
    float hx = __bfloat162float(__ushort_as_bfloat16((unsigned short)(hi & 0xFFFF)));
    float hy = __bfloat162float(__ushort_as_bfloat16((unsigned short)(hi >> 16)));
    __nv_bfloat16 lx = __float2bfloat16(x - hx), ly = __float2bfloat16(y - hy);
    return (uint32_t)__bfloat16_as_ushort(lx) | ((uint32_t)__bfloat16_as_ushort(ly) << 16);
}

// ---------------- hi/lo-split bf16 tensor-core GEMM (mma.sync) ----------------
// C[M,N] (=|+=) A[M,K] @ B[K,N]; fp32 I/O; error ~2^-17.
// CTA 128x64, 256 threads (8 warps, 4x2), K chunked by 32.
// Requires M%128==0, K%32==0, N%8==0 handled by padding (loads masked).
#define GPITCH 40            // bf16 elements per smem row (80B: conflict-free ldmatrix)
template<bool ACC>
__global__ void __launch_bounds__(256) mma_gemm(
    const float* __restrict__ A, int lda,
    const float* __restrict__ B, int ldb,
    float* __restrict__ C, int ldc, int N, int K)
{
    __shared__ __nv_bfloat16 As[2][128 * GPITCH];   // [hi/lo]
    __shared__ __nv_bfloat16 Bs[2][64 * GPITCH];    // stored [n][k]
    const int tid  = threadIdx.x;
    const int wid  = tid >> 5, lane = tid & 31;
    const int row0 = blockIdx.y * 128;
    const int col0 = blockIdx.x * 64;
    const int m_off = (wid & 3) * 32;
    const int n_off = (wid >> 2) * 32;

    float acc[2][4][4];
    #pragma unroll
    for (int mt = 0; mt < 2; mt++)
        #pragma unroll
        for (int nt = 0; nt < 4; nt++)
            #pragma unroll
            for (int i = 0; i < 4; i++) acc[mt][nt][i] = 0.f;

    const int j = lane >> 3, r = lane & 7;
    const int a_loff = ((j & 1) * 8 + r) * (GPITCH * 2) + (j >> 1) * 16;   // bytes
    const int b_loff = ((j >> 1) * 8 + r) * (GPITCH * 2) + (j & 1) * 16;

    uint32_t sA[2] = { smem_u32(As[0]), smem_u32(As[1]) };
    uint32_t sB[2] = { smem_u32(Bs[0]), smem_u32(Bs[1]) };

    for (int k0 = 0; k0 < K; k0 += 32) {
        // ---- stage A chunk: 128 rows x 32 k (float4 per thread x4) ----
        #pragma unroll
        for (int i = 0; i < 4; i++) {
            int idx = tid + i * 256;
            int rr = idx >> 3, c4 = (idx & 7) << 2;
            float4 v = *(const float4*)(A + (size_t)(row0 + rr) * lda + k0 + c4);
            uint2 hv, lv;
            hv.x = pack_hi2(v.x, v.y); lv.x = pack_lo2(v.x, v.y, hv.x);
            hv.y = pack_hi2(v.z, v.w); lv.y = pack_lo2(v.z, v.w, hv.y);
            int boff = rr * (GPITCH * 2) + c4 * 2;
            *(uint2*)((char*)As[0] + boff) = hv;
            *(uint2*)((char*)As[1] + boff) = lv;
        }
        // ---- stage B chunk transposed: [n][k], 32 k x 64 n ----
        #pragma unroll
        for (int i = 0; i < 8; i++) {
            int idx = tid + i * 256;
            int n = idx & 63, k = idx >> 6;
            float v = (col0 + n < N) ? B[(size_t)(k0 + k) * ldb + col0 + n] : 0.f;
            __nv_bfloat16 h = __float2bfloat16(v);
            __nv_bfloat16 l = __float2bfloat16(v - __bfloat162float(h));
            Bs[0][n * GPITCH + k] = h;
            Bs[1][n * GPITCH + k] = l;
        }
        __syncthreads();
        #pragma unroll
        for (int kk = 0; kk < 32; kk += 16) {
            uint32_t afr[2][2][4];     // [mt][hi/lo]
            #pragma unroll
            for (int mt = 0; mt < 2; mt++)
                #pragma unroll
                for (int h = 0; h < 2; h++)
                    ldm4(afr[mt][h], sA[h] + (m_off + mt * 16) * (GPITCH * 2) + kk * 2 + a_loff);
            uint32_t bfr[2][2][4];     // [npair][hi/lo]; r0=b0(n0-7) r1=b1(n0-7) r2=b0(n8-15) r3=b1
            #pragma unroll
            for (int np = 0; np < 2; np++)
                #pragma unroll
                for (int h = 0; h < 2; h++)
                    ldm4(bfr[np][h], sB[h] + (n_off + np * 16) * (GPITCH * 2) + kk * 2 + b_loff);
            #pragma unroll
            for (int mt = 0; mt < 2; mt++)
                #pragma unroll
                for (int nt = 0; nt < 4; nt++) {
                    const uint32_t* bh = &bfr[nt >> 1][0][(nt & 1) * 2];
                    const uint32_t* bl = &bfr[nt >> 1][1][(nt & 1) * 2];
                    mma16816(acc[mt][nt], afr[mt][0], bh);   // hi*hi
                    mma16816(acc[mt][nt], afr[mt][0], bl);   // hi*lo
                    mma16816(acc[mt][nt], afr[mt][1], bh);   // lo*hi
                }
        }
        __syncthreads();
    }
    // ---- epilogue ----
    #pragma unroll
    for (int mt = 0; mt < 2; mt++) {
        #pragma unroll
        for (int nt = 0; nt < 4; nt++) {
            int rbase = row0 + m_off + mt * 16 + (lane >> 2);
            int cc = col0 + n_off + nt * 8 + (lane & 3) * 2;
            if (cc < N) {               // N%8==0 -> tile-granular guard
                float2* p0 = (float2*)(C + (size_t)rbase * ldc + cc);
                float2* p1 = (float2*)(C + (size_t)(rbase + 8) * ldc + cc);
                if (ACC) {
                    float2 o0 = *p0, o1 = *p1;
                    o0.x += acc[mt][nt][0]; o0.y += acc[mt][nt][1];
                    o1.x += acc[mt][nt][2]; o1.y += acc[mt][nt][3];
                    *p0 = o0; *p1 = o1;
                } else {
                    *p0 = make_float2(acc[mt][nt][0], acc[mt][nt][1]);
                    *p1 = make_float2(acc[mt][nt][2], acc[mt][nt][3]);
                }
            }
        }
    }
}

// ---------------- 1) front: h = LN(x @ proj_w + proj_b) ----------------
__global__ void front_kernel(const float* __restrict__ x,  const float* __restrict__ pw,
                             const float* __restrict__ pb, const float* __restrict__ lw,
                             const float* __restrict__ lb) {
    int row = blockIdx.x;
    int pd  = threadIdx.x;         // 64
    __shared__ float xr[DIN];
    __shared__ float red[2];
    if (pd < DIN) xr[pd] = x[row * DIN + pd];
    __syncthreads();
    float acc = pb[pd];
    #pragma unroll
    for (int i = 0; i < DIN; i++) acc = fmaf(xr[i], pw[i * PD + pd], acc);
    float s = acc;
    #pragma unroll
    for (int o = 16; o > 0; o >>= 1) s += __shfl_xor_sync(0xffffffffu, s, o);
    if ((pd & 31) == 0) red[pd >> 5] = s;
    __syncthreads();
    float mu = (red[0] + red[1]) * (1.0f / PD);
    __syncthreads();
    float d = acc - mu;
    float q = d * d;
    #pragma unroll
    for (int o = 16; o > 0; o >>= 1) q += __shfl_xor_sync(0xffffffffu, q, o);
    if ((pd & 31) == 0) red[pd >> 5] = q;
    __syncthreads();
    float var = (red[0] + red[1]) * (1.0f / PD);
    g_h[row * PD + pd] = d * rsqrtf(var + 1e-5f) * lw[pd] + lb[pd];
}

// ---------------- 2) patch embed ----------------
__global__ void patch_kernel(const float* __restrict__ patch_w, const float* __restrict__ patch_b) {
    int n  = blockIdx.x;
    int m  = blockIdx.y;
    int dm = threadIdx.x;          // 128
    int b  = m >> 6, pd = m & 63;
    __shared__ float hv[PL];
    if (dm < PL) hv[dm] = g_h[(b * KSEQ + n * STR + dm) * PD + pd];
    __syncthreads();
    float acc = patch_b[dm];
    #pragma unroll
    for (int pl = 0; pl < PL; pl++) acc = fmaf(hv[pl], patch_w[pl * DM + dm], acc);
    g_e[((size_t)m * NSEQ + n) * DM + dm] = acc;
}

// ---------------- 3) per-token RMS norm ----------------
__global__ void rms_kernel(const float* __restrict__ nw) {
    size_t tok = blockIdx.x;
    int j = threadIdx.x;           // 128
    __shared__ float red[4];
    float v = g_e[tok * DM + j];
    float ss = block_reduce_128(v * v, red);
    g_xr[tok * DM + j] = v * rsqrtf(ss * (1.0f / DM) + 1e-5f) * nw[j];
}

// ---------------- 4) depthwise causal conv (DC=4) + SiLU ----------------
__global__ void conv_kernel(const float* __restrict__ cw, const float* __restrict__ cb) {
    int m = blockIdx.x;            // MSEQ
    int d = threadIdx.x;           // DI
    float w0 = cw[d * DC + 0], w1 = cw[d * DC + 1], w2 = cw[d * DC + 2], w3 = cw[d * DC + 3];
    float bias = cb[d];
    float x0 = 0.f, x1 = 0.f, x2 = 0.f;
    const float* up = g_uz + (size_t)m * NSEQ * 2 * DI + d;
    float*       op = g_u  + (size_t)m * NSEQ * DI + d;
    for (int t = 0; t < NSEQ; t++) {
        float xt = up[(size_t)t * 2 * DI];
        float uc = bias;
        uc = fmaf(x0, w0, uc);
        uc = fmaf(x1, w1, uc);
        uc = fmaf(x2, w2, uc);
        uc = fmaf(xt, w3, uc);
        op[(size_t)t * DI] = fsilu(uc);
        x0 = x1; x1 = x2; x2 = xt;
    }
}

// ---------------- 5) fused dt-proj + softplus + selective scan + gate ----------
__global__ void scan_kernel(const float* __restrict__ dtw, const float* __restrict__ dtbp,
                            const float* __restrict__ alog, const float* __restrict__ dpp) {
    int m = blockIdx.x;            // MSEQ
    int d = threadIdx.x;           // DI
    __shared__ float s_dtw[DTR * DI];
    __shared__ float s40[2][XPJ];
    for (int i = d; i < DTR * DI; i += DI) s_dtw[i] = dtw[i];
    float dtb = dtbp[d];
    float Dpv = dpp[d];
    bool fast = true;
    #pragma unroll
    for (int s = 0; s < DS; s++) {
        float as = -fexp(alog[d * DS + s]);
        fast = fast && (fabsf(as + (float)(s + 1)) < 1e-3f);
    }
    float hst[DS];
    #pragma unroll
    for (int s = 0; s < DS; s++) hst[s] = 0.f;

    const float* dbc = g_dbc + (size_t)m * NSEQ * XPJ;
    if (d < XPJ) s40[0][d] = dbc[d];
    __syncthreads();

    for (int t = 0; t < NSEQ; t++) {
        int cur = t & 1;
        if (t + 1 < NSEQ && d < XPJ) s40[cur ^ 1][d] = dbc[(size_t)(t + 1) * XPJ + d];
        float u_td = g_u[((size_t)m * NSEQ + t) * DI + d];
        float v = dtb;
        #pragma unroll
        for (int i = 0; i < DTR; i++) v = fmaf(s40[cur][i], s_dtw[i * DI + d], v);
        float delta = (v > 15.f) ? v : flog(1.0f + fexp(v));
        float du = delta * u_td;
        float y = 0.f;
        if (fast) {
            float rr = fexp(-delta);
            float p = rr;
            #pragma unroll
            for (int s = 0; s < DS; s++) {
                hst[s] = fmaf(p, hst[s], du * s40[cur][DTR + s]);
                y = fmaf(hst[s], s40[cur][DTR + DS + s], y);
                p *= rr;
            }
        } else {
            #pragma unroll
            for (int s = 0; s < DS; s++) {
                float as = -fexp(alog[d * DS + s]);
                float dA = fexp(delta * as);
                hst[s] = fmaf(dA, hst[s], du * s40[cur][DTR + s]);
                y = fmaf(hst[s], s40[cur][DTR + DS + s], y);
            }
        }
        float yo = fmaf(u_td, Dpv, y);
        float z = g_uz[((size_t)m * NSEQ + t) * 2 * DI + DI + d];
        g_xr[((size_t)m * NSEQ + t) * DI + d] = yo * fsilu(z);
        __syncthreads();
    }
}

// ---------------- 6) final RMS + bb dot per sequence ----------------
__global__ void bb_kernel(const float* __restrict__ fnw, const float* __restrict__ bbw,
                          const float* __restrict__ bbb) {
    int m = blockIdx.x;
    int j = threadIdx.x;           // 128
    __shared__ float red[4];
    float fw = fnw[j];
    float acc = 0.f;
    for (int n = 0; n < NSEQ; n++) {
        float v = g_e[((size_t)m * NSEQ + n) * DM + j];
        float ss = block_reduce_128(v * v, red);
        float scale = rsqrtf(ss * (1.0f / DM) + 1e-5f);
        acc = fmaf(v * scale * fw, bbw[n * DM + j], acc);
    }
    float tot = block_reduce_128(acc, red);
    if (j == 0) g_y1[m] = tot + bbb[0];
}

// ---------------- 7) head ----------------
__global__ void head_kernel(const float* __restrict__ hw, const float* __restrict__ hb,
                            float* __restrict__ out) {
    int t = threadIdx.x;           // 64
    int b = t >> 1, j = t & 1;
    float acc = hb[j];
    #pragma unroll
    for (int p = 0; p < PD; p++) acc = fmaf(g_y1[b * PD + p], hw[p * 2 + j], acc);
    out[b * 2 + j] = acc;
}

// ---------------- launch ----------------
extern "C" void kernel_launch(void* const* d_in, const int* in_sizes, int n_in,
                              void* d_out, int out_size) {
    const float* x       = (const float*)d_in[0];
    const float* proj_w  = (const float*)d_in[1];
    const float* proj_b  = (const float*)d_in[2];
    const float* ln_w    = (const float*)d_in[3];
    const float* ln_b    = (const float*)d_in[4];
    const float* patch_w = (const float*)d_in[5];
    const float* patch_b = (const float*)d_in[6];
    const float* in_w    = (const float*)d_in[7];
    const float* conv_w  = (const float*)d_in[8];
    const float* conv_b  = (const float*)d_in[9];
    const float* xproj_w = (const float*)d_in[10];
    const float* dt_w    = (const float*)d_in[11];
    const float* dt_b    = (const float*)d_in[12];
    const float* A_log   = (const float*)d_in[13];
    const float* Dp      = (const float*)d_in[14];
    const float* out_w   = (const float*)d_in[15];
    const float* norm_w  = (const float*)d_in[16];
    const float* fnorm_w = (const float*)d_in[17];
    const float* bb_w    = (const float*)d_in[18];
    const float* bb_b    = (const float*)d_in[19];
    const float* head_w  = (const float*)d_in[20];
    const float* head_b  = (const float*)d_in[21];
    float* out = (float*)d_out;

    float *xr, *uz, *u, *dbc, *e;
    cudaGetSymbolAddress((void**)&xr,  g_xr);
    cudaGetSymbolAddress((void**)&uz,  g_uz);
    cudaGetSymbolAddress((void**)&u,   g_u);
    cudaGetSymbolAddress((void**)&dbc, g_dbc);
    cudaGetSymbolAddress((void**)&e,   g_e);

    front_kernel<<<BATCH * KSEQ, PD>>>(x, proj_w, proj_b, ln_w, ln_b);
    patch_kernel<<<dim3(NSEQ, MSEQ), DM>>>(patch_w, patch_b);

    for (int l = 0; l < NL; l++) {
        rms_kernel<<<NTOK, DM>>>(norm_w + l * DM);
        // uz = xr @ in_w[l]   (260096 x 128 x 512)
        mma_gemm<false><<<dim3(8, NTOK / 128), 256>>>(
            xr, DM, in_w + (size_t)l * DM * 2 * DI, 2 * DI, uz, 2 * DI, 2 * DI, DM);
        conv_kernel<<<MSEQ, DI>>>(conv_w + (size_t)l * DI * DC, conv_b + (size_t)l * DI);
        // dbc = u @ xproj_w[l]  (260096 x 256 x 40)
        mma_gemm<false><<<dim3(1, NTOK / 128), 256>>>(
            u, DI, xproj_w + (size_t)l * DI * XPJ, XPJ, dbc, XPJ, XPJ, DI);
        scan_kernel<<<MSEQ, DI>>>(dt_w + (size_t)l * DTR * DI, dt_b + (size_t)l * DI,
                                  A_log + (size_t)l * DI * DS, Dp + (size_t)l * DI);
        // e += y_gated @ out_w[l]  (260096 x 256 x 128)
        mma_gemm<true><<<dim3(2, NTOK / 128), 256>>>(
            xr, DI, out_w + (size_t)l * DI * DM, DM, e, DM, DM, DI);
    }

    bb_kernel<<<MSEQ, DM>>>(fnorm_w, bb_w, bb_b);
    head_kernel<<<1, 64>>>(head_w, head_b, out);
}

// round 5
// speedup vs baseline: 1.7842x; 1.2446x over previous
#include <cuda_runtime.h>
#include <cuda_bf16.h>
#include <cstdint>

// ---------------- problem constants ----------------
#define DIN 32
#define KSEQ 512
#define PD 64
#define DM 128
#define NL 4
#define PL 8
#define STR 4
#define DI 256          // 2*DM
#define DS 16
#define DC 4
#define DTR 8
#define NSEQ 127        // (KSEQ-PL)/STR + 1
#define BATCH 32
#define MSEQ (BATCH*PD)         // 2048 sequences
#define NTOK (MSEQ*NSEQ)        // 260096 tokens
#define XPJ (DTR + 2*DS)        // 40

// ---------------- scratch (device globals) ----------------
__device__ float g_h  [BATCH*KSEQ*PD];
__device__ float g_e  [NTOK*DM];
__device__ float g_uz [NTOK*2*DI];
__device__ float g_dbc[NTOK*XPJ];
__device__ float g_y1 [MSEQ];
// bf16 hi/lo operand buffers (A side): rms out [*,128] or gated scan out [*,256]
__device__ __nv_bfloat16 g_ah[NTOK*DI];
__device__ __nv_bfloat16 g_al[NTOK*DI];
// conv+silu output u (xproj A operand + scan input)
__device__ __nv_bfloat16 g_uh[NTOK*DI];
__device__ __nv_bfloat16 g_ul[NTOK*DI];
// transposed hi/lo weights [n][k]
__device__ __nv_bfloat16 g_wih[NL*2*DI*DM];   // in_w:   n=512, k=128
__device__ __nv_bfloat16 g_wil[NL*2*DI*DM];
__device__ __nv_bfloat16 g_wxh[NL*64*DI];     // xproj:  n=64(pad from 40), k=256
__device__ __nv_bfloat16 g_wxl[NL*64*DI];
__device__ __nv_bfloat16 g_woh[NL*DM*DI];     // out_w:  n=128, k=256
__device__ __nv_bfloat16 g_wol[NL*DM*DI];

// ---------------- FMA-only transcendentals ----------
__device__ __forceinline__ float fexp(float x) {
    x = fminf(fmaxf(x, -87.0f), 87.0f);
    float t  = x * 1.4426950408889634f;
    float fi = floorf(t);
    float f  = t - fi;
    float p  = 1.5252733804059841e-05f;
    p = fmaf(p, f, 1.5403530393381608e-04f);
    p = fmaf(p, f, 1.3333558146428443e-03f);
    p = fmaf(p, f, 9.6181291076284770e-03f);
    p = fmaf(p, f, 5.5504108664821580e-02f);
    p = fmaf(p, f, 2.4022650695910070e-01f);
    p = fmaf(p, f, 6.9314718055994530e-01f);
    p = fmaf(p, f, 1.0f);
    int ei = (int)fi;
    float sc = __int_as_float((ei + 127) << 23);
    return p * sc;
}

__device__ __forceinline__ float flog(float x) {
    int ix = __float_as_int(x);
    int e  = ((ix >> 23) & 0xFF) - 127;
    float m = __int_as_float((ix & 0x007FFFFF) | 0x3F800000);
    if (m > 1.41421356f) { m *= 0.5f; e += 1; }
    float f = m - 1.0f;
    float z = f * f;
    float p = 7.0376836292e-2f;
    p = fmaf(p, f, -1.1514610310e-1f);
    p = fmaf(p, f,  1.1676998740e-1f);
    p = fmaf(p, f, -1.2420140846e-1f);
    p = fmaf(p, f,  1.4249322787e-1f);
    p = fmaf(p, f, -1.6668057665e-1f);
    p = fmaf(p, f,  2.0000714765e-1f);
    p = fmaf(p, f, -2.4999993993e-1f);
    p = fmaf(p, f,  3.3333331174e-1f);
    float r = f * z * p - 0.5f * z + f;
    return fmaf((float)e, 0.693147180559945f, r);
}

__device__ __forceinline__ float frcp_pos(float a) {
    float x = __int_as_float(0x7EF311C3 - __float_as_int(a));
    x = x * (2.0f - a * x);
    x = x * (2.0f - a * x);
    x = x * (2.0f - a * x);
    return x;
}

__device__ __forceinline__ float fsigmoid(float x) { return frcp_pos(1.0f + fexp(-x)); }
__device__ __forceinline__ float fsilu(float x)    { return x * fsigmoid(x); }

__device__ __forceinline__ float block_reduce_128(float v, float* red) {
    #pragma unroll
    for (int o = 16; o > 0; o >>= 1) v += __shfl_xor_sync(0xffffffffu, v, o);
    int w = threadIdx.x >> 5;
    __syncthreads();
    if ((threadIdx.x & 31) == 0) red[w] = v;
    __syncthreads();
    return red[0] + red[1] + red[2] + red[3];
}

// ---------------- MMA helpers ----------
__device__ __forceinline__ uint32_t smem_u32(const void* p) {
    uint32_t a;
    asm("{ .reg .u64 t; cvta.to.shared.u64 t, %1; cvt.u32.u64 %0, t; }" : "=r"(a) : "l"(p));
    return a;
}

__device__ __forceinline__ void ldm4(uint32_t* r, uint32_t addr) {
    asm volatile("ldmatrix.sync.aligned.m8n8.x4.shared.b16 {%0,%1,%2,%3}, [%4];"
                 : "=r"(r[0]), "=r"(r[1]), "=r"(r[2]), "=r"(r[3]) : "r"(addr));
}

__device__ __forceinline__ void mma16816(float* c, const uint32_t* a, const uint32_t* b) {
    asm volatile(
        "mma.sync.aligned.m16n8k16.row.col.f32.bf16.bf16.f32 "
        "{%0,%1,%2,%3}, {%4,%5,%6,%7}, {%8,%9}, {%0,%1,%2,%3};"
        : "+f"(c[0]), "+f"(c[1]), "+f"(c[2]), "+f"(c[3])
        : "r"(a[0]), "r"(a[1]), "r"(a[2]), "r"(a[3]), "r"(b[0]), "r"(b[1]));
}

__device__ __forceinline__ void cp16(uint32_t dst, const void* src) {
    asm volatile("cp.async.cg.shared.global [%0], [%1], 16;" :: "r"(dst), "l"(src));
}
__device__ __forceinline__ void cp_commit() { asm volatile("cp.async.commit_group;"); }

// ---------------- double-buffered bf16 hi/lo tensor-core GEMM ----------------
// C[M,Nvalid] (=|+=) (Ah+Al)[M,K] @ (Bh+Bl)^T, B stored [n][k].
// CTA 128 x NTILE, 256 thr (8 warps 4x2), K chunk 32, 2-stage cp.async.
// M%128==0, K%32==0, B padded to NTILE cols with zeros.
#define GP 80    // smem row pitch bytes (40 bf16, conflict-free ldmatrix)
template<int NTILE, bool ACC>
__global__ void __launch_bounds__(256, 2) mma_gemm(
    const __nv_bfloat16* __restrict__ Ah, const __nv_bfloat16* __restrict__ Al, int lda,
    const __nv_bfloat16* __restrict__ Bh, const __nv_bfloat16* __restrict__ Bl, int ldb,
    float* __restrict__ C, int ldc, int Nvalid, int K)
{
    constexpr int WARP_N = NTILE / 2;
    constexpr int NT8    = WARP_N / 8;
    constexpr int ASZ    = 2 * 128 * GP;          // 20480
    constexpr int BSZ    = 2 * NTILE * GP;
    constexpr int SS     = ASZ + BSZ;             // stage stride (bytes)
    extern __shared__ char smem[];
    const uint32_t sb = smem_u32(smem);
    const int tid  = threadIdx.x;
    const int wid  = tid >> 5, lane = tid & 31;
    const int row0 = blockIdx.y * 128;
    const int col0 = blockIdx.x * NTILE;
    const int m_off = (wid & 3) * 32;
    const int n_off = (wid >> 2) * WARP_N;

    const int j = lane >> 3, r = lane & 7;
    const int a_loff = ((j & 1) * 8 + r) * GP + (j >> 1) * 16;
    const int b_loff = ((j >> 1) * 8 + r) * GP + (j & 1) * 16;

    float acc[2][NT8][4];
    #pragma unroll
    for (int mt = 0; mt < 2; mt++)
        #pragma unroll
        for (int nt = 0; nt < NT8; nt++)
            #pragma unroll
            for (int i = 0; i < 4; i++) acc[mt][nt][i] = 0.f;

    auto stage = [&](int st, int k0) {
        uint32_t base = sb + st * SS;
        #pragma unroll
        for (int i = 0; i < 4; i++) {                    // A: 1024 x 16B
            int idx = tid + i * 256;
            int h = idx >> 9, rr = (idx >> 2) & 127, c = idx & 3;
            const __nv_bfloat16* src = (h ? Al : Ah) + (size_t)(row0 + rr) * lda + k0 + c * 8;
            cp16(base + h * (128 * GP) + rr * GP + c * 16, src);
        }
        #pragma unroll
        for (int i = 0; i < NTILE / 32; i++) {           // B: NTILE*8 x 16B
            int idx = tid + i * 256;
            int h = idx >= NTILE * 4;
            int id2 = idx & (NTILE * 4 - 1);
            int n = id2 >> 2, c = id2 & 3;
            const __nv_bfloat16* src = (h ? Bl : Bh) + (size_t)(col0 + n) * ldb + k0 + c * 8;
            cp16(base + ASZ + h * (NTILE * GP) + n * GP + c * 16, src);
        }
        cp_commit();
    };

    const int nk = K / 32;
    stage(0, 0);
    for (int i = 0; i < nk; i++) {
        if (i + 1 < nk) {
            stage((i + 1) & 1, (i + 1) * 32);
            asm volatile("cp.async.wait_group 1;" ::: "memory");
        } else {
            asm volatile("cp.async.wait_group 0;" ::: "memory");
        }
        __syncthreads();
        uint32_t base = sb + (i & 1) * SS;
        uint32_t sA[2] = { base, base + 128 * GP };
        uint32_t sB[2] = { base + ASZ, base + ASZ + NTILE * GP };
        #pragma unroll
        for (int kk = 0; kk < 32; kk += 16) {
            uint32_t afr[2][2][4];
            #pragma unroll
            for (int mt = 0; mt < 2; mt++)
                #pragma unroll
                for (int h = 0; h < 2; h++)
                    ldm4(afr[mt][h], sA[h] + (m_off + mt * 16) * GP + kk * 2 + a_loff);
            uint32_t bfr[NTILE / 32][2][4];
            #pragma unroll
            for (int np = 0; np < NTILE / 32; np++)
                #pragma unroll
                for (int h = 0; h < 2; h++)
                    ldm4(bfr[np][h], sB[h] + (n_off + np * 16) * GP + kk * 2 + b_loff);
            #pragma unroll
            for (int mt = 0; mt < 2; mt++)
                #pragma unroll
                for (int nt = 0; nt < NT8; nt++) {
                    const uint32_t* bh = &bfr[nt >> 1][0][(nt & 1) * 2];
                    const uint32_t* bl = &bfr[nt >> 1][1][(nt & 1) * 2];
                    mma16816(acc[mt][nt], afr[mt][0], bh);
                    mma16816(acc[mt][nt], afr[mt][0], bl);
                    mma16816(acc[mt][nt], afr[mt][1], bh);
                }
        }
        __syncthreads();
    }
    // ---- epilogue ----
    #pragma unroll
    for (int mt = 0; mt < 2; mt++) {
        #pragma unroll
        for (int nt = 0; nt < NT8; nt++) {
            int rbase = row0 + m_off + mt * 16 + (lane >> 2);
            int cc = col0 + n_off + nt * 8 + (lane & 3) * 2;
            if (cc < Nvalid) {
                float2* p0 = (float2*)(C + (size_t)rbase * ldc + cc);
                float2* p1 = (float2*)(C + (size_t)(rbase + 8) * ldc + cc);
                if (ACC) {
                    float2 o0 = *p0, o1 = *p1;
                    o0.x += acc[mt][nt][0]; o0.y += acc[mt][nt][1];
                    o1.x += acc[mt][nt][2]; o1.y += acc[mt][nt][3];
                    *p0 = o0; *p1 = o1;
                } else {
                    *p0 = make_float2(acc[mt][nt][0], acc[mt][nt][1]);
                    *p1 = make_float2(acc[mt][nt][2], acc[mt][nt][3]);
                }
            }
        }
    }
}

// ---------------- weight convert + transpose: src[k][n] fp32 -> dst[n][k] hi/lo ----
__global__ void wconv_kernel(const float* __restrict__ src, __nv_bfloat16* __restrict__ dh,
                             __nv_bfloat16* __restrict__ dl, int K, int Nsrc, int Npad) {
    int idx = blockIdx.x * 256 + threadIdx.x;
    if (idx >= Npad * K) return;
    int n = idx / K, k = idx - n * K;
    float v = (n < Nsrc) ? src[(size_t)k * Nsrc + n] : 0.f;
    __nv_bfloat16 h = __float2bfloat16(v);
    dh[idx] = h;
    dl[idx] = __float2bfloat16(v - __bfloat162float(h));
}

// ---------------- 1) front: h = LN(x @ proj_w + proj_b) ----------------
__global__ void front_kernel(const float* __restrict__ x,  const float* __restrict__ pw,
                             const float* __restrict__ pb, const float* __restrict__ lw,
                             const float* __restrict__ lb) {
    int row = blockIdx.x;
    int pd  = threadIdx.x;         // 64
    __shared__ float xr[DIN];
    __shared__ float red[2];
    if (pd < DIN) xr[pd] = x[row * DIN + pd];
    __syncthreads();
    float acc = pb[pd];
    #pragma unroll
    for (int i = 0; i < DIN; i++) acc = fmaf(xr[i], pw[i * PD + pd], acc);
    float s = acc;
    #pragma unroll
    for (int o = 16; o > 0; o >>= 1) s += __shfl_xor_sync(0xffffffffu, s, o);
    if ((pd & 31) == 0) red[pd >> 5] = s;
    __syncthreads();
    float mu = (red[0] + red[1]) * (1.0f / PD);
    __syncthreads();
    float d = acc - mu;
    float q = d * d;
    #pragma unroll
    for (int o = 16; o > 0; o >>= 1) q += __shfl_xor_sync(0xffffffffu, q, o);
    if ((pd & 31) == 0) red[pd >> 5] = q;
    __syncthreads();
    float var = (red[0] + red[1]) * (1.0f / PD);
    g_h[row * PD + pd] = d * rsqrtf(var + 1e-5f) * lw[pd] + lb[pd];
}

// ---------------- 2) patch embed ----------------
__global__ void patch_kernel(const float* __restrict__ patch_w, const float* __restrict__ patch_b) {
    int n  = blockIdx.x;
    int m  = blockIdx.y;
    int dm = threadIdx.x;          // 128
    int b  = m >> 6, pd = m & 63;
    __shared__ float hv[PL];
    if (dm < PL) hv[dm] = g_h[(b * KSEQ + n * STR + dm) * PD + pd];
    __syncthreads();
    float acc = patch_b[dm];
    #pragma unroll
    for (int pl = 0; pl < PL; pl++) acc = fmaf(hv[pl], patch_w[pl * DM + dm], acc);
    g_e[((size_t)m * NSEQ + n) * DM + dm] = acc;
}

// ---------------- 3) RMS norm (warp/token) -> bf16 hi/lo ----------------
__global__ void rms_kernel(const float* __restrict__ nw) {
    int w = threadIdx.x >> 5, l = threadIdx.x & 31;
    size_t tok = (size_t)blockIdx.x * 8 + w;
    float4 v = *(const float4*)(g_e + tok * DM + l * 4);
    float ss = v.x * v.x + v.y * v.y + v.z * v.z + v.w * v.w;
    #pragma unroll
    for (int o = 16; o > 0; o >>= 1) ss += __shfl_xor_sync(0xffffffffu, ss, o);
    float sc = rsqrtf(ss * (1.0f / DM) + 1e-5f);
    float4 nwv = *(const float4*)(nw + l * 4);
    float a0 = v.x * sc * nwv.x, a1 = v.y * sc * nwv.y;
    float a2 = v.z * sc * nwv.z, a3 = v.w * sc * nwv.w;
    __nv_bfloat16 h0 = __float2bfloat16(a0), h1 = __float2bfloat16(a1);
    __nv_bfloat16 h2 = __float2bfloat16(a2), h3 = __float2bfloat16(a3);
    uint2 hv, lv;
    hv.x = (uint32_t)__bfloat16_as_ushort(h0) | ((uint32_t)__bfloat16_as_ushort(h1) << 16);
    hv.y = (uint32_t)__bfloat16_as_ushort(h2) | ((uint32_t)__bfloat16_as_ushort(h3) << 16);
    __nv_bfloat16 l0 = __float2bfloat16(a0 - __bfloat162float(h0));
    __nv_bfloat16 l1 = __float2bfloat16(a1 - __bfloat162float(h1));
    __nv_bfloat16 l2 = __float2bfloat16(a2 - __bfloat162float(h2));
    __nv_bfloat16 l3 = __float2bfloat16(a3 - __bfloat162float(h3));
    lv.x = (uint32_t)__bfloat16_as_ushort(l0) | ((uint32_t)__bfloat16_as_ushort(l1) << 16);
    lv.y = (uint32_t)__bfloat16_as_ushort(l2) | ((uint32_t)__bfloat16_as_ushort(l3) << 16);
    *(uint2*)(g_ah + tok * DM + l * 4) = hv;
    *(uint2*)(g_al + tok * DM + l * 4) = lv;
}

// ---------------- 4) depthwise causal conv + SiLU -> bf16 hi/lo ----------------
__global__ void conv_kernel(const float* __restrict__ cw, const float* __restrict__ cb) {
    int m = blockIdx.x;            // MSEQ
    int d = threadIdx.x;           // DI
    float w0 = cw[d * DC + 0], w1 = cw[d * DC + 1], w2 = cw[d * DC + 2], w3 = cw[d * DC + 3];
    float bias = cb[d];
    float x0 = 0.f, x1 = 0.f, x2 = 0.f;
    const float* up = g_uz + (size_t)m * NSEQ * 2 * DI + d;
    size_t ob = (size_t)m * NSEQ * DI + d;
    for (int t = 0; t < NSEQ; t++) {
        float xt = up[(size_t)t * 2 * DI];
        float uc = bias;
        uc = fmaf(x0, w0, uc);
        uc = fmaf(x1, w1, uc);
        uc = fmaf(x2, w2, uc);
        uc = fmaf(xt, w3, uc);
        float u = fsilu(uc);
        __nv_bfloat16 h = __float2bfloat16(u);
        g_uh[ob + (size_t)t * DI] = h;
        g_ul[ob + (size_t)t * DI] = __float2bfloat16(u - __bfloat162float(h));
        x0 = x1; x1 = x2; x2 = xt;
    }
}

// ---------------- 5) fused dt-proj + softplus + scan + gate -> bf16 hi/lo --------
__global__ void scan_kernel(const float* __restrict__ dtw, const float* __restrict__ dtbp,
                            const float* __restrict__ alog, const float* __restrict__ dpp) {
    int m = blockIdx.x;            // MSEQ
    int d = threadIdx.x;           // DI
    __shared__ float buf[2][8][XPJ];
    float wreg[DTR];
    #pragma unroll
    for (int i = 0; i < DTR; i++) wreg[i] = dtw[i * DI + d];
    float dtb = dtbp[d];
    float Dpv = dpp[d];
    bool fast = true;
    #pragma unroll
    for (int s = 0; s < DS; s++) {
        float as = -fexp(alog[d * DS + s]);
        fast = fast && (fabsf(as + (float)(s + 1)) < 1e-3f);
    }
    float hst[DS];
    #pragma unroll
    for (int s = 0; s < DS; s++) hst[s] = 0.f;

    const float* dbc = g_dbc + (size_t)m * NSEQ * XPJ;
    for (int idx = d; idx < 8 * XPJ; idx += DI)
        buf[0][idx / XPJ][idx % XPJ] = dbc[idx];
    __syncthreads();

    const int NTILES = (NSEQ + 7) / 8;   // 16
    for (int jt = 0; jt < NTILES; jt++) {
        int t0 = jt * 8;
        int cnt = min(8, NSEQ - t0);
        if (jt + 1 < NTILES) {
            int t1 = t0 + 8;
            int cnt1 = min(8, NSEQ - t1);
            for (int idx = d; idx < cnt1 * XPJ; idx += DI)
                buf[(jt + 1) & 1][idx / XPJ][idx % XPJ] = dbc[(size_t)t1 * XPJ + idx];
        }
        const float* bj = &buf[jt & 1][0][0];
        for (int tt = 0; tt < cnt; tt++) {
            int t = t0 + tt;
            const float* s40 = bj + tt * XPJ;
            size_t off = ((size_t)m * NSEQ + t) * DI + d;
            float u_td = __bfloat162float(g_uh[off]) + __bfloat162float(g_ul[off]);
            float v = dtb;
            #pragma unroll
            for (int i = 0; i < DTR; i++) v = fmaf(s40[i], wreg[i], v);
            float delta = (v > 15.f) ? v : flog(1.0f + fexp(v));
            float du = delta * u_td;
            float y = 0.f;
            if (fast) {
                float rr = fexp(-delta);
                float p = rr;
                #pragma unroll
                for (int s = 0; s < DS; s++) {
                    hst[s] = fmaf(p, hst[s], du * s40[DTR + s]);
                    y = fmaf(hst[s], s40[DTR + DS + s], y);
                    p *= rr;
                }
            } else {
                #pragma unroll
                for (int s = 0; s < DS; s++) {
                    float as = -fexp(alog[d * DS + s]);
                    float dA = fexp(delta * as);
                    hst[s] = fmaf(dA, hst[s], du * s40[DTR + s]);
                    y = fmaf(hst[s], s40[DTR + DS + s], y);
                }
            }
            float yo = fmaf(u_td, Dpv, y);
            float z = g_uz[((size_t)m * NSEQ + t) * 2 * DI + DI + d];
            float yg = yo * fsilu(z);
            __nv_bfloat16 h = __float2bfloat16(yg);
            g_ah[off] = h;
            g_al[off] = __float2bfloat16(yg - __bfloat162float(h));
        }
        __syncthreads();
    }
}

// ---------------- 6) final RMS + bb dot ----------------
__global__ void bb_kernel(const float* __restrict__ fnw, const float* __restrict__ bbw,
                          const float* __restrict__ bbb) {
    int m = blockIdx.x;
    int jj = threadIdx.x;          // 128
    __shared__ float red[4];
    float fw = fnw[jj];
    float acc = 0.f;
    for (int n = 0; n < NSEQ; n++) {
        float v = g_e[((size_t)m * NSEQ + n) * DM + jj];
        float ss = block_reduce_128(v * v, red);
        float scale = rsqrtf(ss * (1.0f / DM) + 1e-5f);
        acc = fmaf(v * scale * fw, bbw[n * DM + jj], acc);
    }
    float tot = block_reduce_128(acc, red);
    if (jj == 0) g_y1[m] = tot + bbb[0];
}

// ---------------- 7) head ----------------
__global__ void head_kernel(const float* __restrict__ hw, const float* __restrict__ hb,
                            float* __restrict__ out) {
    int t = threadIdx.x;           // 64
    int b = t >> 1, jj = t & 1;
    float acc = hb[jj];
    #pragma unroll
    for (int p = 0; p < PD; p++) acc = fmaf(g_y1[b * PD + p], hw[p * 2 + jj], acc);
    out[b * 2 + jj] = acc;
}

// ---------------- launch ----------------
extern "C" void kernel_launch(void* const* d_in, const int* in_sizes, int n_in,
                              void* d_out, int out_size) {
    const float* x       = (const float*)d_in[0];
    const float* proj_w  = (const float*)d_in[1];
    const float* proj_b  = (const float*)d_in[2];
    const float* ln_w    = (const float*)d_in[3];
    const float* ln_b    = (const float*)d_in[4];
    const float* patch_w = (const float*)d_in[5];
    const float* patch_b = (const float*)d_in[6];
    const float* in_w    = (const float*)d_in[7];
    const float* conv_w  = (const float*)d_in[8];
    const float* conv_b  = (const float*)d_in[9];
    const float* xproj_w = (const float*)d_in[10];
    const float* dt_w    = (const float*)d_in[11];
    const float* dt_b    = (const float*)d_in[12];
    const float* A_log   = (const float*)d_in[13];
    const float* Dp      = (const float*)d_in[14];
    const float* out_w   = (const float*)d_in[15];
    const float* norm_w  = (const float*)d_in[16];
    const float* fnorm_w = (const float*)d_in[17];
    const float* bb_w    = (const float*)d_in[18];
    const float* bb_b    = (const float*)d_in[19];
    const float* head_w  = (const float*)d_in[20];
    const float* head_b  = (const float*)d_in[21];
    float* out = (float*)d_out;

    float *uz, *dbc, *e;
    __nv_bfloat16 *ah, *al, *uh, *ul, *wih, *wil, *wxh, *wxl, *woh, *wol;
    cudaGetSymbolAddress((void**)&uz,  g_uz);
    cudaGetSymbolAddress((void**)&dbc, g_dbc);
    cudaGetSymbolAddress((void**)&e,   g_e);
    cudaGetSymbolAddress((void**)&ah,  g_ah);
    cudaGetSymbolAddress((void**)&al,  g_al);
    cudaGetSymbolAddress((void**)&uh,  g_uh);
    cudaGetSymbolAddress((void**)&ul,  g_ul);
    cudaGetSymbolAddress((void**)&wih, g_wih);
    cudaGetSymbolAddress((void**)&wil, g_wil);
    cudaGetSymbolAddress((void**)&wxh, g_wxh);
    cudaGetSymbolAddress((void**)&wxl, g_wxl);
    cudaGetSymbolAddress((void**)&woh, g_woh);
    cudaGetSymbolAddress((void**)&wol, g_wol);

    const int SMEM128 = 2 * (20480 + 2 * 128 * GP);   // 81920
    const int SMEM64  = 2 * (20480 + 2 * 64 * GP);    // 61440
    cudaFuncSetAttribute(mma_gemm<128, false>, cudaFuncAttributeMaxDynamicSharedMemorySize, SMEM128);
    cudaFuncSetAttribute(mma_gemm<128, true>,  cudaFuncAttributeMaxDynamicSharedMemorySize, SMEM128);
    cudaFuncSetAttribute(mma_gemm<64,  false>, cudaFuncAttributeMaxDynamicSharedMemorySize, SMEM64);

    // weight conversion (transposed hi/lo), per layer
    for (int l = 0; l < NL; l++) {
        wconv_kernel<<<(2 * DI * DM + 255) / 256, 256>>>(
            in_w + (size_t)l * DM * 2 * DI, wih + (size_t)l * 2 * DI * DM,
            wil + (size_t)l * 2 * DI * DM, DM, 2 * DI, 2 * DI);
        wconv_kernel<<<(64 * DI + 255) / 256, 256>>>(
            xproj_w + (size_t)l * DI * XPJ, wxh + (size_t)l * 64 * DI,
            wxl + (size_t)l * 64 * DI, DI, XPJ, 64);
        wconv_kernel<<<(DM * DI + 255) / 256, 256>>>(
            out_w + (size_t)l * DI * DM, woh + (size_t)l * DM * DI,
            wol + (size_t)l * DM * DI, DI, DM, DM);
    }

    front_kernel<<<BATCH * KSEQ, PD>>>(x, proj_w, proj_b, ln_w, ln_b);
    patch_kernel<<<dim3(NSEQ, MSEQ), DM>>>(patch_w, patch_b);

    for (int l = 0; l < NL; l++) {
        rms_kernel<<<NTOK / 8, 256>>>(norm_w + l * DM);
        // uz = xr @ in_w[l]   (260096 x 128 x 512)
        mma_gemm<128, false><<<dim3(4, NTOK / 128), 256, SMEM128>>>(
            ah, al, DM, wih + (size_t)l * 2 * DI * DM, wil + (size_t)l * 2 * DI * DM, DM,
            uz, 2 * DI, 2 * DI, DM);
        conv_kernel<<<MSEQ, DI>>>(conv_w + (size_t)l * DI * DC, conv_b + (size_t)l * DI);
        // dbc = u @ xproj_w[l]  (260096 x 256 x 40)
        mma_gemm<64, false><<<dim3(1, NTOK / 128), 256, SMEM64>>>(
            uh, ul, DI, wxh + (size_t)l * 64 * DI, wxl + (size_t)l * 64 * DI, DI,
            dbc, XPJ, XPJ, DI);
        scan_kernel<<<MSEQ, DI>>>(dt_w + (size_t)l * DTR * DI, dt_b + (size_t)l * DI,
                                  A_log + (size_t)l * DI * DS, Dp + (size_t)l * DI);
        // e += y_gated @ out_w[l]  (260096 x 256 x 128)
        mma_gemm<128, true><<<dim3(1, NTOK / 128), 256, SMEM128>>>(
            ah, al, DI, woh + (size_t)l * DM * DI, wol + (size_t)l * DM * DI, DI,
            e, DM, DM, DI);
    }

    bb_kernel<<<MSEQ, DM>>>(fnorm_w, bb_w, bb_b);
    head_kernel<<<1, 64>>>(head_w, head_b, out);
}